// round 1
// baseline (speedup 1.0000x reference)
#include <cuda_runtime.h>
#include <math.h>

// Problem constants (from reference: features [8,64,100000], coords [8,3,100000], R=32)
constexpr int B = 8;
constexpr int C = 64;
constexpr int N = 100000;
constexpr int R = 32;
constexpr int V = R * R * R;   // 32768

// Scratch (allocation-free rule: __device__ globals)
__device__ float        g_scratch[(size_t)B * V * C];  // [b][voxel][c]  64 MB
__device__ int          g_count[B * V];
__device__ float        g_mean[B * 3];
__device__ unsigned int g_radbits[B];

// ---------------------------------------------------------------------------
__global__ void zero_kernel() {
    const size_t total4 = (size_t)B * V * C / 4;
    float4* p = reinterpret_cast<float4*>(g_scratch);
    const float4 z = make_float4(0.f, 0.f, 0.f, 0.f);
    const size_t stride = (size_t)gridDim.x * blockDim.x;
    for (size_t i = (size_t)blockIdx.x * blockDim.x + threadIdx.x; i < total4; i += stride)
        p[i] = z;
    const int tid = blockIdx.x * blockDim.x + threadIdx.x;
    for (int i = tid; i < B * V; i += (int)stride)
        g_count[i] = 0;
    if (tid < B)
        g_radbits[tid] = 0u;
}

// ---------------------------------------------------------------------------
// One block per (batch, dim): sum 100000 floats -> mean
__global__ void mean_kernel(const float* __restrict__ coords) {
    const int b = blockIdx.x / 3, d = blockIdx.x % 3;
    const float* p = coords + ((size_t)b * 3 + d) * N;
    float s = 0.f;
    for (int i = threadIdx.x; i < N; i += blockDim.x)
        s += p[i];
    __shared__ float sh[512];
    sh[threadIdx.x] = s;
    __syncthreads();
    for (int k = blockDim.x >> 1; k > 0; k >>= 1) {
        if (threadIdx.x < k) sh[threadIdx.x] += sh[threadIdx.x + k];
        __syncthreads();
    }
    if (threadIdx.x == 0)
        g_mean[b * 3 + d] = sh[0] * (1.0f / (float)N);
}

// ---------------------------------------------------------------------------
// Max squared radius per batch (sqrt applied once later; exact vs reference
// because sqrt is monotone & correctly rounded, so it commutes with max)
__global__ void radius_kernel(const float* __restrict__ coords) {
    const int b = blockIdx.y;
    const float mx = g_mean[b * 3 + 0];
    const float my = g_mean[b * 3 + 1];
    const float mz = g_mean[b * 3 + 2];
    const float* p = coords + (size_t)b * 3 * N;
    float best = 0.f;
    for (int i = blockIdx.x * blockDim.x + threadIdx.x; i < N;
         i += gridDim.x * blockDim.x) {
        float x = p[i]         - mx;
        float y = p[i + N]     - my;
        float z = p[i + 2 * N] - mz;
        float s = x * x + y * y + z * z;
        best = fmaxf(best, s);
    }
#pragma unroll
    for (int o = 16; o; o >>= 1)
        best = fmaxf(best, __shfl_xor_sync(0xffffffffu, best, o));
    __shared__ float sh[32];
    const int lane = threadIdx.x & 31, w = threadIdx.x >> 5;
    if (lane == 0) sh[w] = best;
    __syncthreads();
    if (threadIdx.x == 0) {
        float m = sh[0];
        for (int i = 1; i < (int)(blockDim.x >> 5); i++)
            m = fmaxf(m, sh[i]);
        // nonnegative floats: bit pattern order == value order
        atomicMax(&g_radbits[b], __float_as_uint(m));
    }
}

// ---------------------------------------------------------------------------
// Vector RED: 4 consecutive f32 accumulated with one L2 atomic op
__device__ __forceinline__ void red_add_v4(float* addr, float4 v) {
    asm volatile("red.global.add.v4.f32 [%0], {%1, %2, %3, %4};"
                 :: "l"(addr), "f"(v.x), "f"(v.y), "f"(v.z), "f"(v.w)
                 : "memory");
}

// One thread per (batch, point): write norm_coords, bump count, scatter all
// 64 channels into channel-contiguous scratch via 16 v4 REDs.
__global__ void scatter_kernel(const float* __restrict__ features,
                               const float* __restrict__ coords,
                               float* __restrict__ out_norm) {
    const int b = blockIdx.y;
    const int n = blockIdx.x * blockDim.x + threadIdx.x;
    if (n >= N) return;

    const float mx = g_mean[b * 3 + 0];
    const float my = g_mean[b * 3 + 1];
    const float mz = g_mean[b * 3 + 2];
    const float denom = 2.0f * sqrtf(__uint_as_float(g_radbits[b]));  // EPS = 0

    const float* p = coords + (size_t)b * 3 * N;
    float vx = (p[n]         - mx) / denom + 0.5f;
    float vy = (p[n + N]     - my) / denom + 0.5f;
    float vz = (p[n + 2 * N] - mz) / denom + 0.5f;
    vx = fminf(fmaxf(vx * (float)R, 0.f), (float)(R - 1));
    vy = fminf(fmaxf(vy * (float)R, 0.f), (float)(R - 1));
    vz = fminf(fmaxf(vz * (float)R, 0.f), (float)(R - 1));

    float* on = out_norm + (size_t)b * 3 * N;
    on[n]         = vx;
    on[n + N]     = vy;
    on[n + 2 * N] = vz;

    // jnp.round == round-half-to-even == rintf
    const int ix = (int)rintf(vx);
    const int iy = (int)rintf(vy);
    const int iz = (int)rintf(vz);
    const int idx = (ix * R + iy) * R + iz;

    atomicAdd(&g_count[b * V + idx], 1);

    float* dst = g_scratch + ((size_t)b * V + idx) * C;   // 256B-aligned row
    const float* f = features + (size_t)b * C * N + n;
#pragma unroll
    for (int c = 0; c < C; c += 4) {
        float4 v;
        v.x = f[(size_t)(c + 0) * N];
        v.y = f[(size_t)(c + 1) * N];
        v.z = f[(size_t)(c + 2) * N];
        v.w = f[(size_t)(c + 3) * N];
        red_add_v4(dst + c, v);
    }
}

// ---------------------------------------------------------------------------
// Transpose [b][v][c] -> [b][c][v] with count division. 32 voxels x 64 ch
// tile in smem, padded stride 65 for conflict-free transposed reads.
__global__ void finalize_kernel(float* __restrict__ out_grid) {
    __shared__ float tile[32][65];
    __shared__ float rinv[32];

    const int b  = blockIdx.x >> 10;            // V/32 = 1024 chunks per batch
    const int v0 = (blockIdx.x & 1023) * 32;
    const int t  = threadIdx.x;                 // 256 threads

    const float* src = g_scratch + ((size_t)b * V + v0) * C;
#pragma unroll
    for (int k = 0; k < 8; k++) {
        int e = t + k * 256;                    // 2048 elements
        tile[e >> 6][e & 63] = src[e];
    }
    if (t < 32) {
        int c = g_count[b * V + v0 + t];
        rinv[t] = 1.0f / (float)(c > 1 ? c : 1);
    }
    __syncthreads();

    float* dst = out_grid + (size_t)b * C * V + v0;
#pragma unroll
    for (int k = 0; k < 8; k++) {
        int e  = t + k * 256;
        int c  = e >> 5;                        // 0..63
        int vl = e & 31;                        // 0..31
        dst[(size_t)c * V + vl] = tile[vl][c] * rinv[vl];
    }
}

// ---------------------------------------------------------------------------
extern "C" void kernel_launch(void* const* d_in, const int* in_sizes, int n_in,
                              void* d_out, int out_size) {
    const float* features = (const float*)d_in[0];
    const float* coords   = (const float*)d_in[1];
    float* out_grid = (float*)d_out;                      // [B,C,V]
    float* out_norm = (float*)d_out + (size_t)B * C * V;  // [B,3,N]

    zero_kernel<<<2048, 256>>>();
    mean_kernel<<<B * 3, 512>>>(coords);
    radius_kernel<<<dim3(48, B), 256>>>(coords);
    scatter_kernel<<<dim3((N + 255) / 256, B), 256>>>(features, coords, out_norm);
    finalize_kernel<<<B * (V / 32), 256>>>(out_grid);
}

// round 2
// speedup vs baseline: 1.4812x; 1.4812x over previous
#include <cuda_runtime.h>
#include <math.h>

// Problem constants (features [8,64,100000], coords [8,3,100000], R=32)
constexpr int B = 8;
constexpr int C = 64;
constexpr int N = 100000;
constexpr int R = 32;
constexpr int V = R * R * R;   // 32768
constexpr int BP = 128;        // points per scatter block

// Scratch (allocation-free rule: __device__ globals)
__device__ float        g_scratch[(size_t)B * V * C];  // [b][voxel][c]  64 MB
__device__ int          g_count[B * V];
__device__ float        g_mean[B * 3];
__device__ unsigned int g_radbits[B];

// ---------------------------------------------------------------------------
__global__ void zero_kernel() {
    const size_t total4 = (size_t)B * V * C / 4;
    float4* p = reinterpret_cast<float4*>(g_scratch);
    const float4 z = make_float4(0.f, 0.f, 0.f, 0.f);
    const size_t stride = (size_t)gridDim.x * blockDim.x;
    for (size_t i = (size_t)blockIdx.x * blockDim.x + threadIdx.x; i < total4; i += stride)
        p[i] = z;
    const int tid = blockIdx.x * blockDim.x + threadIdx.x;
    for (int i = tid; i < B * V; i += (int)stride)
        g_count[i] = 0;
    if (tid < B * 3)
        g_mean[tid] = 0.f;
    if (tid < B)
        g_radbits[tid] = 0u;
}

// ---------------------------------------------------------------------------
// Partial sums + float atomicAdd -> g_mean (zeroed by zero_kernel).
__global__ void mean_kernel(const float* __restrict__ coords) {
    const int b = blockIdx.y / 3, d = blockIdx.y % 3;
    const float* p = coords + ((size_t)b * 3 + d) * N;
    float s = 0.f;
    for (int i = blockIdx.x * blockDim.x + threadIdx.x; i < N;
         i += gridDim.x * blockDim.x)
        s += p[i];
#pragma unroll
    for (int o = 16; o; o >>= 1)
        s += __shfl_xor_sync(0xffffffffu, s, o);
    __shared__ float sh[8];
    const int lane = threadIdx.x & 31, w = threadIdx.x >> 5;
    if (lane == 0) sh[w] = s;
    __syncthreads();
    if (threadIdx.x == 0) {
        float m = 0.f;
        for (int i = 0; i < (int)(blockDim.x >> 5); i++) m += sh[i];
        atomicAdd(&g_mean[b * 3 + d], m * (1.0f / (float)N));
    }
}

// ---------------------------------------------------------------------------
// Max squared radius per batch (sqrt commutes with max: monotone + correctly
// rounded, so applying sqrt once later is exact vs the reference).
__global__ void radius_kernel(const float* __restrict__ coords) {
    const int b = blockIdx.y;
    const float mx = g_mean[b * 3 + 0];
    const float my = g_mean[b * 3 + 1];
    const float mz = g_mean[b * 3 + 2];
    const float* p = coords + (size_t)b * 3 * N;
    float best = 0.f;
    for (int i = blockIdx.x * blockDim.x + threadIdx.x; i < N;
         i += gridDim.x * blockDim.x) {
        float x = p[i]         - mx;
        float y = p[i + N]     - my;
        float z = p[i + 2 * N] - mz;
        best = fmaxf(best, x * x + y * y + z * z);
    }
#pragma unroll
    for (int o = 16; o; o >>= 1)
        best = fmaxf(best, __shfl_xor_sync(0xffffffffu, best, o));
    __shared__ float sh[8];
    const int lane = threadIdx.x & 31, w = threadIdx.x >> 5;
    if (lane == 0) sh[w] = best;
    __syncthreads();
    if (threadIdx.x == 0) {
        float m = sh[0];
        for (int i = 1; i < (int)(blockDim.x >> 5); i++) m = fmaxf(m, sh[i]);
        atomicMax(&g_radbits[b], __float_as_uint(m));  // nonneg: bit order == value order
    }
}

// ---------------------------------------------------------------------------
__device__ __forceinline__ void red_add_v4(float* addr, float4 v) {
    asm volatile("red.global.add.v4.f32 [%0], {%1, %2, %3, %4};"
                 :: "l"(addr), "f"(v.x), "f"(v.y), "f"(v.z), "f"(v.w)
                 : "memory");
}

// Scatter with smem staging: load features coalesced (thread = point), then
// remap so each RED instruction covers 2 points x 64 channels with
// half-warp-contiguous addresses (256B per voxel row) -> ~16x fewer L1tex
// wavefronts than per-lane scattered REDs.
__global__ __launch_bounds__(BP) void scatter_kernel(
        const float* __restrict__ features,
        const float* __restrict__ coords,
        float* __restrict__ out_norm) {
    __shared__ float4 sfeat[BP][17];   // row stride 17 float4 (68 f): conflict-free
    __shared__ int    sidx[BP];

    const int b = blockIdx.y;
    const int t = threadIdx.x;
    const int n = blockIdx.x * BP + t;

    int idx = -1;
    if (n < N) {
        const float mx = g_mean[b * 3 + 0];
        const float my = g_mean[b * 3 + 1];
        const float mz = g_mean[b * 3 + 2];
        const float denom = 2.0f * sqrtf(__uint_as_float(g_radbits[b]));  // EPS=0

        const float* p = coords + (size_t)b * 3 * N;
        float vx = (p[n]         - mx) / denom + 0.5f;
        float vy = (p[n + N]     - my) / denom + 0.5f;
        float vz = (p[n + 2 * N] - mz) / denom + 0.5f;
        vx = fminf(fmaxf(vx * (float)R, 0.f), (float)(R - 1));
        vy = fminf(fmaxf(vy * (float)R, 0.f), (float)(R - 1));
        vz = fminf(fmaxf(vz * (float)R, 0.f), (float)(R - 1));

        float* on = out_norm + (size_t)b * 3 * N;
        on[n]         = vx;
        on[n + N]     = vy;
        on[n + 2 * N] = vz;

        // jnp.round == round-half-to-even == rintf
        idx = ((int)rintf(vx) * R + (int)rintf(vy)) * R + (int)rintf(vz);
        atomicAdd(&g_count[b * V + idx], 1);

        // Coalesced feature load (lanes = consecutive points), stage to smem
        const float* f = features + (size_t)b * C * N + n;
        float4* row = &sfeat[t][0];
#pragma unroll
        for (int c = 0; c < C; c += 4) {
            float4 v;
            v.x = f[(size_t)(c + 0) * N];
            v.y = f[(size_t)(c + 1) * N];
            v.z = f[(size_t)(c + 2) * N];
            v.w = f[(size_t)(c + 3) * N];
            row[c >> 2] = v;
        }
    }
    sidx[t] = idx;
    __syncthreads();

    // RED phase: warp w owns points [w*32, w*32+32). Each iteration: 2 points,
    // lanes 0-15 -> point A channels 4*cl.., lanes 16-31 -> point B.
    const int w    = t >> 5;
    const int lane = t & 31;
    const int half = lane >> 4;
    const int cl   = lane & 15;
    float* base = g_scratch + (size_t)b * V * C;
#pragma unroll
    for (int j = 0; j < 16; j++) {
        const int p  = w * 32 + j * 2 + half;
        const int vi = sidx[p];
        if (vi >= 0) {
            float4 v = sfeat[p][cl];
            red_add_v4(base + (size_t)vi * C + 4 * cl, v);
        }
    }
}

// ---------------------------------------------------------------------------
// Transpose [b][v][c] -> [b][c][v] with count division. 32 voxels x 64 ch
// smem tile, padded stride 65 for conflict-free transposed reads.
__global__ void finalize_kernel(float* __restrict__ out_grid) {
    __shared__ float tile[32][65];
    __shared__ float rinv[32];

    const int b  = blockIdx.x >> 10;            // V/32 = 1024 chunks per batch
    const int v0 = (blockIdx.x & 1023) * 32;
    const int t  = threadIdx.x;                 // 256 threads

    const float* src = g_scratch + ((size_t)b * V + v0) * C;
#pragma unroll
    for (int k = 0; k < 8; k++) {
        int e = t + k * 256;                    // 2048 elements
        tile[e >> 6][e & 63] = src[e];
    }
    if (t < 32) {
        int c = g_count[b * V + v0 + t];
        rinv[t] = 1.0f / (float)(c > 1 ? c : 1);
    }
    __syncthreads();

    float* dst = out_grid + (size_t)b * C * V + v0;
#pragma unroll
    for (int k = 0; k < 8; k++) {
        int e  = t + k * 256;
        int c  = e >> 5;                        // 0..63
        int vl = e & 31;                        // 0..31
        dst[(size_t)c * V + vl] = tile[vl][c] * rinv[vl];
    }
}

// ---------------------------------------------------------------------------
extern "C" void kernel_launch(void* const* d_in, const int* in_sizes, int n_in,
                              void* d_out, int out_size) {
    const float* features = (const float*)d_in[0];
    const float* coords   = (const float*)d_in[1];
    float* out_grid = (float*)d_out;                      // [B,C,V]
    float* out_norm = (float*)d_out + (size_t)B * C * V;  // [B,3,N]

    zero_kernel<<<2048, 256>>>();
    mean_kernel<<<dim3(16, B * 3), 256>>>(coords);
    radius_kernel<<<dim3(48, B), 256>>>(coords);
    scatter_kernel<<<dim3((N + BP - 1) / BP, B), BP>>>(features, coords, out_norm);
    finalize_kernel<<<B * (V / 32), 256>>>(out_grid);
}

// round 3
// speedup vs baseline: 1.5888x; 1.0726x over previous
#include <cuda_runtime.h>
#include <math.h>

// Problem constants (features [8,64,100000], coords [8,3,100000], R=32)
constexpr int B = 8;
constexpr int C = 64;
constexpr int N = 100000;
constexpr int R = 32;
constexpr int V = R * R * R;   // 32768
constexpr int BP = 128;        // points per scatter block
constexpr int CHUNK = 32;      // points staged per chunk

// Scratch (allocation-free rule: __device__ globals)
__device__ float        g_scratch[(size_t)B * V * C];  // [b][voxel][c]  64 MB
__device__ int          g_count[B * V];
__device__ int          g_idx[B * N];                  // per-point voxel index
__device__ float        g_mean[B * 3];
__device__ unsigned int g_radbits[B];

// ---------------------------------------------------------------------------
__global__ void zero_kernel() {
    const size_t total4 = (size_t)B * V * C / 4;
    float4* p = reinterpret_cast<float4*>(g_scratch);
    const float4 z = make_float4(0.f, 0.f, 0.f, 0.f);
    const size_t stride = (size_t)gridDim.x * blockDim.x;
    for (size_t i = (size_t)blockIdx.x * blockDim.x + threadIdx.x; i < total4; i += stride)
        p[i] = z;
    const int tid = blockIdx.x * blockDim.x + threadIdx.x;
    for (int i = tid; i < B * V; i += (int)stride)
        g_count[i] = 0;
    if (tid < B * 3)
        g_mean[tid] = 0.f;
    if (tid < B)
        g_radbits[tid] = 0u;
}

// ---------------------------------------------------------------------------
// Partial sums + float atomicAdd -> g_mean (zeroed by zero_kernel).
__global__ void mean_kernel(const float* __restrict__ coords) {
    const int b = blockIdx.y / 3, d = blockIdx.y % 3;
    const float* p = coords + ((size_t)b * 3 + d) * N;
    float s = 0.f;
    for (int i = blockIdx.x * blockDim.x + threadIdx.x; i < N;
         i += gridDim.x * blockDim.x)
        s += p[i];
#pragma unroll
    for (int o = 16; o; o >>= 1)
        s += __shfl_xor_sync(0xffffffffu, s, o);
    __shared__ float sh[8];
    const int lane = threadIdx.x & 31, w = threadIdx.x >> 5;
    if (lane == 0) sh[w] = s;
    __syncthreads();
    if (threadIdx.x == 0) {
        float m = 0.f;
        for (int i = 0; i < (int)(blockDim.x >> 5); i++) m += sh[i];
        atomicAdd(&g_mean[b * 3 + d], m * (1.0f / (float)N));
    }
}

// ---------------------------------------------------------------------------
// Max squared radius per batch (sqrt commutes with max: monotone + correctly
// rounded, so applying sqrt once later is exact vs the reference).
__global__ void radius_kernel(const float* __restrict__ coords) {
    const int b = blockIdx.y;
    const float mx = g_mean[b * 3 + 0];
    const float my = g_mean[b * 3 + 1];
    const float mz = g_mean[b * 3 + 2];
    const float* p = coords + (size_t)b * 3 * N;
    float best = 0.f;
    for (int i = blockIdx.x * blockDim.x + threadIdx.x; i < N;
         i += gridDim.x * blockDim.x) {
        float x = p[i]         - mx;
        float y = p[i + N]     - my;
        float z = p[i + 2 * N] - mz;
        best = fmaxf(best, x * x + y * y + z * z);
    }
#pragma unroll
    for (int o = 16; o; o >>= 1)
        best = fmaxf(best, __shfl_xor_sync(0xffffffffu, best, o));
    __shared__ float sh[8];
    const int lane = threadIdx.x & 31, w = threadIdx.x >> 5;
    if (lane == 0) sh[w] = best;
    __syncthreads();
    if (threadIdx.x == 0) {
        float m = sh[0];
        for (int i = 1; i < (int)(blockDim.x >> 5); i++) m = fmaxf(m, sh[i]);
        atomicMax(&g_radbits[b], __float_as_uint(m));  // nonneg: bit order == value order
    }
}

// ---------------------------------------------------------------------------
// Per-point: norm coords (output), voxel index, count bump.
__global__ void voxidx_kernel(const float* __restrict__ coords,
                              float* __restrict__ out_norm) {
    const int b = blockIdx.y;
    const int n = blockIdx.x * blockDim.x + threadIdx.x;
    if (n >= N) return;

    const float mx = g_mean[b * 3 + 0];
    const float my = g_mean[b * 3 + 1];
    const float mz = g_mean[b * 3 + 2];
    const float denom = 2.0f * sqrtf(__uint_as_float(g_radbits[b]));  // EPS=0

    const float* p = coords + (size_t)b * 3 * N;
    float vx = (p[n]         - mx) / denom + 0.5f;
    float vy = (p[n + N]     - my) / denom + 0.5f;
    float vz = (p[n + 2 * N] - mz) / denom + 0.5f;
    vx = fminf(fmaxf(vx * (float)R, 0.f), (float)(R - 1));
    vy = fminf(fmaxf(vy * (float)R, 0.f), (float)(R - 1));
    vz = fminf(fmaxf(vz * (float)R, 0.f), (float)(R - 1));

    float* on = out_norm + (size_t)b * 3 * N;
    on[n]         = vx;
    on[n + N]     = vy;
    on[n + 2 * N] = vz;

    // jnp.round == round-half-to-even == rintf
    const int idx = ((int)rintf(vx) * R + (int)rintf(vy)) * R + (int)rintf(vz);
    g_idx[b * N + n] = idx;
    atomicAdd(&g_count[b * V + idx], 1);
}

// ---------------------------------------------------------------------------
__device__ __forceinline__ void red_add_v4(float* addr, float4 v) {
    asm volatile("red.global.add.v4.f32 [%0], {%1, %2, %3, %4};"
                 :: "l"(addr), "f"(v.x), "f"(v.y), "f"(v.z), "f"(v.w)
                 : "memory");
}

// Feature scatter. Stages CHUNK=32 points (8.7 KB smem) per round so 12
// blocks fit per SM (75% occupancy). Loads coalesced (lanes = consecutive
// points, warp w covers channels 16w..16w+15); REDs issued so each
// instruction covers 2 points x 64 channels, half-warp-contiguous 256B rows.
__global__ __launch_bounds__(BP, 12) void scatter_kernel(
        const float* __restrict__ features) {
    __shared__ float4 tile[CHUNK][17];   // stride 17 float4: conflict-free
    __shared__ int    sidx[CHUNK];

    const int b    = blockIdx.y;
    const int n0   = blockIdx.x * BP;
    const int t    = threadIdx.x;
    const int w    = t >> 5;
    const int lane = t & 31;
    const int half = lane >> 4;
    const int cl   = lane & 15;

    const float* fb   = features + (size_t)b * C * N;
    float*       base = g_scratch + (size_t)b * V * C;
    const int*   ib   = g_idx + b * N;

#pragma unroll
    for (int ch = 0; ch < BP / CHUNK; ch++) {
        const int nc = n0 + ch * CHUNK;

        if (t < CHUNK)
            sidx[t] = (nc + t < N) ? ib[nc + t] : -1;

        const int n = nc + lane;
        if (n < N) {
            // warp w loads channels [16w, 16w+16) for its lane's point
            const float* f = fb + n + (size_t)(16 * w) * N;
#pragma unroll
            for (int q = 0; q < 4; q++) {
                float4 v;
                v.x = f[0];
                v.y = f[(size_t)N];
                v.z = f[(size_t)2 * N];
                v.w = f[(size_t)3 * N];
                tile[lane][4 * w + q] = v;
                f += (size_t)4 * N;
            }
        }
        __syncthreads();

        // warp w reduces points [8w, 8w+8): 4 iters x 2 points
#pragma unroll
        for (int j = 0; j < 4; j++) {
            const int p  = 8 * w + 2 * j + half;
            const int vi = sidx[p];
            if (vi >= 0) {
                float4 v = tile[p][cl];
                red_add_v4(base + (size_t)vi * C + 4 * cl, v);
            }
        }
        __syncthreads();
    }
}

// ---------------------------------------------------------------------------
// Transpose [b][v][c] -> [b][c][v] with count division. 32 voxels x 64 ch
// smem tile, padded stride 65 for conflict-free transposed reads.
__global__ void finalize_kernel(float* __restrict__ out_grid) {
    __shared__ float tile[32][65];
    __shared__ float rinv[32];

    const int b  = blockIdx.x >> 10;            // V/32 = 1024 chunks per batch
    const int v0 = (blockIdx.x & 1023) * 32;
    const int t  = threadIdx.x;                 // 256 threads

    const float4* src4 = reinterpret_cast<const float4*>(
        g_scratch + ((size_t)b * V + v0) * C);  // 512 float4
#pragma unroll
    for (int k = 0; k < 2; k++) {
        int e = t + k * 256;
        float4 v = src4[e];
        int row = e >> 4;            // voxel 0..31
        int col = (e & 15) * 4;      // channel 0..60
        tile[row][col + 0] = v.x;
        tile[row][col + 1] = v.y;
        tile[row][col + 2] = v.z;
        tile[row][col + 3] = v.w;
    }
    if (t < 32) {
        int c = g_count[b * V + v0 + t];
        rinv[t] = 1.0f / (float)(c > 1 ? c : 1);
    }
    __syncthreads();

    float* dst = out_grid + (size_t)b * C * V + v0;
#pragma unroll
    for (int k = 0; k < 8; k++) {
        int e  = t + k * 256;
        int c  = e >> 5;                        // 0..63
        int vl = e & 31;                        // 0..31
        dst[(size_t)c * V + vl] = tile[vl][c] * rinv[vl];
    }
}

// ---------------------------------------------------------------------------
extern "C" void kernel_launch(void* const* d_in, const int* in_sizes, int n_in,
                              void* d_out, int out_size) {
    const float* features = (const float*)d_in[0];
    const float* coords   = (const float*)d_in[1];
    float* out_grid = (float*)d_out;                      // [B,C,V]
    float* out_norm = (float*)d_out + (size_t)B * C * V;  // [B,3,N]

    zero_kernel<<<2048, 256>>>();
    mean_kernel<<<dim3(16, B * 3), 256>>>(coords);
    radius_kernel<<<dim3(48, B), 256>>>(coords);
    voxidx_kernel<<<dim3((N + 255) / 256, B), 256>>>(coords, out_norm);
    scatter_kernel<<<dim3((N + BP - 1) / BP, B), BP>>>(features);
    finalize_kernel<<<B * (V / 32), 256>>>(out_grid);
}